// round 9
// baseline (speedup 1.0000x reference)
#include <cuda_runtime.h>
#include <cuda_bf16.h>
#include <math.h>
#include <stdint.h>

// Problem constants
#define RB 256      // batch
#define RT 512      // time steps
#define RH 1024     // hidden
#define RC 10       // classes

// Tiling: 4 batch groups (M=64) x 32 j-tiles (N=32) = 128 CTAs (1 per SM)
#define NM 4
#define NN 32
#define MT 64
#define NT 32
#define KC 128             // k per staged chunk
#define NCH 8              // chunks per step
#define NTH 256            // 8 warps

// SMEM byte layout (dynamic)
// W rows padded to 2064B (1032 bf16) for conflict-free ldmatrix (8-row stride)
#define W_PITCH 2064
#define SW_HI 0
#define SW_LO 66048
#define SA_OFF 132096
// A chunk: 64 rows x 272B (128 bf16 data + 16B pad) = 17408 per split
#define A_PITCH 272
#define A_SPLIT 17408
#define A_BUF 34816                      // hi + lo
#define SMEM_BYTES (SA_OFF + 2 * A_BUF)  // 201728

// Persistent state (device globals; no allocation)
__device__ __nv_bfloat16 g_hh[2][RB * RH];   // h hi, [b][k]
__device__ __nv_bfloat16 g_hl[2][RB * RH];   // h lo
__device__ float g_xT[RT * RB];              // x transposed: [t][b]
__device__ unsigned int g_cnt[NM][NCH][8];   // per-(group, k-chunk) counters (padded)

// ----------------- helpers -----------------
__device__ __forceinline__ uint32_t smem_u32(const void* p) {
    uint32_t a;
    asm("{ .reg .u64 t; cvta.to.shared.u64 t, %1; cvt.u32.u64 %0, t; }"
        : "=r"(a) : "l"(p));
    return a;
}

__device__ __forceinline__ void ldsm4(uint32_t addr, uint32_t r[4]) {
    asm volatile("ldmatrix.sync.aligned.m8n8.x4.shared.b16 {%0,%1,%2,%3}, [%4];"
                 : "=r"(r[0]), "=r"(r[1]), "=r"(r[2]), "=r"(r[3]) : "r"(addr));
}

__device__ __forceinline__ void mma_bf16(float d[4], const uint32_t a[4],
                                         uint32_t b0, uint32_t b1) {
    asm volatile(
        "mma.sync.aligned.m16n8k16.row.col.f32.bf16.bf16.f32 "
        "{%0,%1,%2,%3},{%4,%5,%6,%7},{%8,%9},{%0,%1,%2,%3};"
        : "+f"(d[0]), "+f"(d[1]), "+f"(d[2]), "+f"(d[3])
        : "r"(a[0]), "r"(a[1]), "r"(a[2]), "r"(a[3]), "r"(b0), "r"(b1));
}

__device__ __forceinline__ void cp16(uint32_t d, const void* s) {
    asm volatile("cp.async.cg.shared.global [%0], [%1], 16;"
                 :: "r"(d), "l"(s) : "memory");
}

__device__ __forceinline__ uint32_t ld_acq(const unsigned int* p) {
    uint32_t v;
    asm volatile("ld.acquire.gpu.global.u32 %0, [%1];" : "=r"(v) : "l"(p)
                 : "memory");
    return v;
}
__device__ __forceinline__ void red_rel_add1(unsigned int* p) {
    asm volatile("red.release.gpu.global.add.u32 [%0], %1;"
                 :: "l"(p), "r"(1u) : "memory");
}

// Accurate tanh independent of fast-math lowering.
__device__ __forceinline__ float tanh_acc(float v) {
    float ax = fabsf(v);
    if (ax < 0.25f) {
        float s = v * v;
        float p = fmaf(s, 0.021869488f, -0.05396825397f);
        p = fmaf(s, p, 0.13333333333f);
        p = fmaf(s, p, -0.33333333333f);
        return fmaf(v * s, p, v);
    } else {
        float e = expf(-2.0f * ax);
        float r = (1.0f - e) / (1.0f + e);
        return copysignf(r, v);
    }
}

// Stage one 64x128 bf16 chunk (hi and lo) into a padded A buffer.
__device__ __forceinline__ void copy_chunk(uint32_t abuf,
                                           const __nv_bfloat16* __restrict__ hh,
                                           const __nv_bfloat16* __restrict__ hl,
                                           int chunk) {
    const int tid = threadIdx.x;
    const __nv_bfloat16* sh = hh + chunk * KC;
    const __nv_bfloat16* sl = hl + chunk * KC;
#pragma unroll
    for (int i = 0; i < 4; ++i) {
        int seg = tid + i * NTH;            // 0..1023: 16B segments
        int row = seg >> 4;                 // 16 segs per 256B row
        int c16 = seg & 15;
        uint32_t doff = (uint32_t)row * A_PITCH + (uint32_t)c16 * 16u;
        const char* gs = (const char*)(sh + (size_t)row * RH) + c16 * 16;
        cp16(abuf + doff, gs);
        const char* gl = (const char*)(sl + (size_t)row * RH) + c16 * 16;
        cp16(abuf + A_SPLIT + doff, gl);
    }
}

__global__ void __launch_bounds__(NTH, 1)
rnn_init_kernel(const float* __restrict__ x) {
    int idx = blockIdx.x * blockDim.x + threadIdx.x;
    if (idx < RB * RH) {
        g_hh[0][idx] = __float2bfloat16(0.0f);
        g_hl[0][idx] = __float2bfloat16(0.0f);
    }
    if (idx < RT * RB) {
        int b = idx & (RB - 1);
        int t = idx >> 8;
        g_xT[idx] = x[(size_t)b * RT + t];
    }
    if (idx < NM * NCH * 8) ((unsigned int*)g_cnt)[idx] = 0u;
}

__global__ void __launch_bounds__(NTH, 1)
rnn_mma_kernel(const float* __restrict__ whx,
               const float* __restrict__ whh,
               const float* __restrict__ bias_h) {
    extern __shared__ char smem[];
    const uint32_t sb = smem_u32(smem);
    const uint32_t swh = sb + SW_HI;
    const uint32_t swl = sb + SW_LO;
    const uint32_t sa = sb + SA_OFF;

    const int tid = threadIdx.x;
    const int wid = tid >> 5;
    const int lane = tid & 31;
    const int bid = blockIdx.x;
    const int m = bid >> 5;              // 0..3 batch group
    const int n = bid & 31;              // 0..31 j tile
    const int jg0 = n * NT;
    const int brow0 = m * MT;
    const int ci0 = n >> 2;              // ring start = own chunk

    const int wm = wid & 3;              // warp m16 tile 0..3
    const int wn = wid >> 2;             // warp n16 tile 0..1

    // whh slice -> resident SMEM, split hi/lo bf16, padded rows.
    for (int idx = tid; idx < NT * (RH / 2); idx += NTH) {
        int jl = idx >> 9;                  // /512
        int k2 = (idx & 511) * 2;
        float2 wv = *reinterpret_cast<const float2*>(
            &whh[(size_t)(jg0 + jl) * RH + k2]);
        __nv_bfloat16 h0 = __float2bfloat16(wv.x);
        __nv_bfloat16 l0 = __float2bfloat16(wv.x - __bfloat162float(h0));
        __nv_bfloat16 h1 = __float2bfloat16(wv.y);
        __nv_bfloat16 l1 = __float2bfloat16(wv.y - __bfloat162float(h1));
        uint32_t off = (uint32_t)jl * W_PITCH + (uint32_t)k2 * 2u;
        __nv_bfloat162 p2h; p2h.x = h0; p2h.y = h1;
        __nv_bfloat162 p2l; p2l.x = l0; p2l.y = l1;
        *reinterpret_cast<__nv_bfloat162*>(smem + SW_HI + off) = p2h;
        *reinterpret_cast<__nv_bfloat162*>(smem + SW_LO + off) = p2l;
    }

    // ldmatrix source addresses
    const uint32_t a_off = (uint32_t)(wm * 16 + (lane & 15)) * A_PITCH +
                           (uint32_t)(lane >> 4) * 16u;
    const int brn = wn * 16 + (lane & 7) + ((lane & 16) ? 8 : 0);
    const uint32_t b_off = (uint32_t)brn * W_PITCH +
                           (uint32_t)((lane >> 3) & 1) * 16u;

    // Epilogue constants
    const int r0 = wm * 16 + (lane >> 2);         // local m row (and +8)
    const int cc = wn * 16 + 2 * (lane & 3);      // local n col (even pair)
    float wx[4], bs[4];
    wx[0] = whx[jg0 + cc];      bs[0] = bias_h[jg0 + cc];
    wx[1] = whx[jg0 + cc + 1];  bs[1] = bias_h[jg0 + cc + 1];
    wx[2] = whx[jg0 + cc + 8];  bs[2] = bias_h[jg0 + cc + 8];
    wx[3] = whx[jg0 + cc + 9];  bs[3] = bias_h[jg0 + cc + 9];
    const int bg0 = brow0 + r0;          // global rows bg0 and bg0+8

    unsigned int* mycnt = &g_cnt[m][ci0][0];

    __syncthreads();

    for (int t = 0; t < RT; ++t) {
        const __nv_bfloat16* hh = &g_hh[t & 1][(size_t)brow0 * RH];
        const __nv_bfloat16* hl = &g_hl[t & 1][(size_t)brow0 * RH];
        const unsigned int need = 4u * (unsigned int)t;

        // Poll readiness of first two ring chunks, then prefetch.
        if (tid == 0) {
            while (ld_acq(&g_cnt[m][ci0][0]) < need) { }
            while (ld_acq(&g_cnt[m][(ci0 + 1) & 7][0]) < need) { }
        }
        __syncthreads();
        copy_chunk(sa, hh, hl, ci0);
        asm volatile("cp.async.commit_group;" ::: "memory");
        copy_chunk(sa + A_BUF, hh, hl, (ci0 + 1) & 7);
        asm volatile("cp.async.commit_group;" ::: "memory");

        float xb0 = g_xT[t * RB + bg0];
        float xb1 = g_xT[t * RB + bg0 + 8];

        float dhh[8], dcr[8];
#pragma unroll
        for (int i = 0; i < 8; ++i) { dhh[i] = 0.f; dcr[i] = 0.f; }

#pragma unroll 1
        for (int c = 0; c < NCH; ++c) {
            const int ci = (ci0 + c) & 7;
            if (c < NCH - 1) asm volatile("cp.async.wait_group 1;" ::: "memory");
            else             asm volatile("cp.async.wait_group 0;" ::: "memory");
            __syncthreads();

            const uint32_t ab = sa + (uint32_t)(c & 1) * A_BUF;
#pragma unroll
            for (int ks = 0; ks < 8; ++ks) {
                uint32_t ahi[4], alo[4], bhi[4], blo[4];
                ldsm4(ab + a_off + (uint32_t)ks * 32u, ahi);
                ldsm4(ab + A_SPLIT + a_off + (uint32_t)ks * 32u, alo);
                uint32_t kb = (uint32_t)(ci * KC + ks * 16) * 2u;
                ldsm4(swh + b_off + kb, bhi);
                ldsm4(swl + b_off + kb, blo);
                mma_bf16(dhh + 0, ahi, bhi[0], bhi[1]);
                mma_bf16(dhh + 4, ahi, bhi[2], bhi[3]);
                // cross terms share one accumulator set:
                mma_bf16(dcr + 0, ahi, blo[0], blo[1]);
                mma_bf16(dcr + 4, ahi, blo[2], blo[3]);
                mma_bf16(dcr + 0, alo, bhi[0], bhi[1]);
                mma_bf16(dcr + 4, alo, bhi[2], bhi[3]);
            }
            // Poll next ring chunk while other warps finish MMA, then sync
            // (sync also protects buffer (c&1) from the upcoming overwrite).
            if (tid == 0 && c + 2 < NCH) {
                while (ld_acq(&g_cnt[m][(ci0 + c + 2) & 7][0]) < need) { }
            }
            __syncthreads();
            if (c + 2 < NCH) {
                copy_chunk(sa + (uint32_t)(c & 1) * A_BUF, hh, hl,
                           (ci0 + c + 2) & 7);
                asm volatile("cp.async.commit_group;" ::: "memory");
            }
        }

        // Epilogue: sum products, add input + bias, tanh, split hi/lo, store.
        const int ob = (t + 1) & 1;
        float v[8];
#pragma unroll
        for (int i = 0; i < 8; ++i) v[i] = dhh[i] + dcr[i];
        float hv[8];
        hv[0] = tanh_acc(v[0] + fmaf(xb0, wx[0], bs[0]));
        hv[1] = tanh_acc(v[1] + fmaf(xb0, wx[1], bs[1]));
        hv[2] = tanh_acc(v[2] + fmaf(xb1, wx[0], bs[0]));
        hv[3] = tanh_acc(v[3] + fmaf(xb1, wx[1], bs[1]));
        hv[4] = tanh_acc(v[4] + fmaf(xb0, wx[2], bs[2]));
        hv[5] = tanh_acc(v[5] + fmaf(xb0, wx[3], bs[3]));
        hv[6] = tanh_acc(v[6] + fmaf(xb1, wx[2], bs[2]));
        hv[7] = tanh_acc(v[7] + fmaf(xb1, wx[3], bs[3]));

#pragma unroll
        for (int g = 0; g < 4; ++g) {
            int rr = bg0 + ((g & 1) ? 8 : 0);
            int jc = jg0 + cc + ((g & 2) ? 8 : 0);
            float a = hv[(g & 2) * 2 + (g & 1) * 2 + 0];
            float b = hv[(g & 2) * 2 + (g & 1) * 2 + 1];
            __nv_bfloat16 ah = __float2bfloat16(a);
            __nv_bfloat16 bh = __float2bfloat16(b);
            __nv_bfloat16 al = __float2bfloat16(a - __bfloat162float(ah));
            __nv_bfloat16 bl = __float2bfloat16(b - __bfloat162float(bh));
            __nv_bfloat162 ph; ph.x = ah; ph.y = bh;
            __nv_bfloat162 pl; pl.x = al; pl.y = bl;
            size_t po = (size_t)rr * RH + jc;
            *reinterpret_cast<__nv_bfloat162*>(&g_hh[ob][po]) = ph;
            *reinterpret_cast<__nv_bfloat162*>(&g_hl[ob][po]) = pl;
        }

        // Publish: all threads' stores -> bar -> release-increment own chunk.
        __syncthreads();
        if (tid == 0) red_rel_add1(mycnt);
    }
}

// p[b][c] = (h_hi + h_lo)[b] . wph[c] + bias_p[c]; final h is in buffer 0.
__global__ void __launch_bounds__(RB, 1)
rnn_proj_kernel(const float* __restrict__ wph,
                const float* __restrict__ bias_p,
                float* __restrict__ out) {
    const int c = blockIdx.x;    // 0..9
    const int b = threadIdx.x;   // 0..255
    const __nv_bfloat16* hh = &g_hh[0][(size_t)b * RH];
    const __nv_bfloat16* hl = &g_hl[0][(size_t)b * RH];
    const float* w = wph + (size_t)c * RH;
    float a0 = 0.0f, a1 = 0.0f;
#pragma unroll 4
    for (int k = 0; k < RH; k += 2) {
        __nv_bfloat162 h2 = *reinterpret_cast<const __nv_bfloat162*>(hh + k);
        __nv_bfloat162 l2 = *reinterpret_cast<const __nv_bfloat162*>(hl + k);
        a0 = fmaf(__bfloat162float(h2.x) + __bfloat162float(l2.x), w[k], a0);
        a1 = fmaf(__bfloat162float(h2.y) + __bfloat162float(l2.y), w[k + 1], a1);
    }
    out[b * RC + c] = a0 + a1 + bias_p[c];
}

extern "C" void kernel_launch(void* const* d_in, const int* in_sizes, int n_in,
                              void* d_out, int out_size) {
    (void)in_sizes; (void)n_in; (void)out_size;
    const float* x      = (const float*)d_in[0];   // [B, T]
    const float* whx    = (const float*)d_in[1];   // [H, 1]
    const float* whh    = (const float*)d_in[2];   // [H, H]
    const float* bias_h = (const float*)d_in[3];   // [H]
    const float* wph    = (const float*)d_in[4];   // [C, H]
    const float* bias_p = (const float*)d_in[5];   // [C]
    float* out = (float*)d_out;                    // [B, C]

    cudaFuncSetAttribute(rnn_mma_kernel,
                         cudaFuncAttributeMaxDynamicSharedMemorySize, SMEM_BYTES);

    rnn_init_kernel<<<(RB * RH + NTH - 1) / NTH, NTH>>>(x);
    rnn_mma_kernel<<<NM * NN, NTH, SMEM_BYTES>>>(whx, whh, bias_h);
    rnn_proj_kernel<<<RC, RB>>>(wph, bias_p, out);
}

// round 10
// speedup vs baseline: 1.1410x; 1.1410x over previous
#include <cuda_runtime.h>
#include <cuda_bf16.h>
#include <math.h>
#include <stdint.h>

// Problem constants
#define RB 256      // batch
#define RT 512      // time steps
#define RH 1024     // hidden
#define RC 10       // classes

// Tiling: 4 batch groups (M=64) x 32 j-tiles (N=32) = 128 CTAs (1 per SM)
#define NM 4
#define NN 32
#define MT 64
#define NT 32
#define KC 128             // k per staged chunk
#define NCH 8              // chunks per step
#define NTH 256            // 8 warps, each owns one k16 slice of a chunk

// SMEM byte layout (dynamic)
// W rows padded to 2064B (1032 bf16) for conflict-free ldmatrix (8-row stride)
#define W_PITCH 2064
#define SW_HI 0
#define SW_LO 66048
#define SA_OFF 132096
// A chunk: 64 rows x 272B (128 bf16 data + 16B pad) = 17408 per split
#define A_PITCH 272
#define A_SPLIT 17408
#define A_BUF 34816                      // hi + lo
// Reduction scratch overlaps A staging: 8 warps x 64 rows x 144B = 73728
#define RED_PITCH 144
#define RED_WARP (64 * RED_PITCH)        // 9216
#define SMEM_BYTES (SA_OFF + 73728)      // 205824

// Persistent state (device globals; no allocation)
__device__ __nv_bfloat16 g_hh[2][RB * RH];   // h hi, [b][k]
__device__ __nv_bfloat16 g_hl[2][RB * RH];   // h lo
__device__ float g_xT[RT * RB];              // x transposed: [t][b]
__device__ unsigned int g_bar[NM];           // per-group monotonic barrier

// ----------------- helpers -----------------
__device__ __forceinline__ uint32_t smem_u32(const void* p) {
    uint32_t a;
    asm("{ .reg .u64 t; cvta.to.shared.u64 t, %1; cvt.u32.u64 %0, t; }"
        : "=r"(a) : "l"(p));
    return a;
}

__device__ __forceinline__ void ldsm4(uint32_t addr, uint32_t r[4]) {
    asm volatile("ldmatrix.sync.aligned.m8n8.x4.shared.b16 {%0,%1,%2,%3}, [%4];"
                 : "=r"(r[0]), "=r"(r[1]), "=r"(r[2]), "=r"(r[3]) : "r"(addr));
}

__device__ __forceinline__ void mma_bf16(float* d, const uint32_t a[4],
                                         uint32_t b0, uint32_t b1) {
    asm volatile(
        "mma.sync.aligned.m16n8k16.row.col.f32.bf16.bf16.f32 "
        "{%0,%1,%2,%3},{%4,%5,%6,%7},{%8,%9},{%0,%1,%2,%3};"
        : "+f"(d[0]), "+f"(d[1]), "+f"(d[2]), "+f"(d[3])
        : "r"(a[0]), "r"(a[1]), "r"(a[2]), "r"(a[3]), "r"(b0), "r"(b1));
}

__device__ __forceinline__ void cp16(uint32_t d, const void* s) {
    asm volatile("cp.async.cg.shared.global [%0], [%1], 16;"
                 :: "r"(d), "l"(s) : "memory");
}

// Accurate tanh independent of fast-math lowering.
__device__ __forceinline__ float tanh_acc(float v) {
    float ax = fabsf(v);
    if (ax < 0.25f) {
        float s = v * v;
        float p = fmaf(s, 0.021869488f, -0.05396825397f);
        p = fmaf(s, p, 0.13333333333f);
        p = fmaf(s, p, -0.33333333333f);
        return fmaf(v * s, p, v);
    } else {
        float e = expf(-2.0f * ax);
        float r = (1.0f - e) / (1.0f + e);
        return copysignf(r, v);
    }
}

// Stage one 64x128 bf16 chunk (hi and lo) into a padded A buffer.
__device__ __forceinline__ void copy_chunk(uint32_t abuf,
                                           const __nv_bfloat16* __restrict__ hh,
                                           const __nv_bfloat16* __restrict__ hl,
                                           int chunk) {
    const int tid = threadIdx.x;
    const __nv_bfloat16* sh = hh + chunk * KC;
    const __nv_bfloat16* sl = hl + chunk * KC;
#pragma unroll
    for (int i = 0; i < 4; ++i) {
        int seg = tid + i * NTH;            // 0..1023: 16B segments
        int row = seg >> 4;                 // 16 segs per 256B row
        int c16 = seg & 15;
        uint32_t doff = (uint32_t)row * A_PITCH + (uint32_t)c16 * 16u;
        const char* gs = (const char*)(sh + (size_t)row * RH) + c16 * 16;
        cp16(abuf + doff, gs);
        const char* gl = (const char*)(sl + (size_t)row * RH) + c16 * 16;
        cp16(abuf + A_SPLIT + doff, gl);
    }
}

__global__ void __launch_bounds__(NTH, 1)
rnn_init_kernel(const float* __restrict__ x) {
    int idx = blockIdx.x * blockDim.x + threadIdx.x;
    if (idx < RB * RH) {
        g_hh[0][idx] = __float2bfloat16(0.0f);
        g_hl[0][idx] = __float2bfloat16(0.0f);
    }
    if (idx < RT * RB) {
        int b = idx & (RB - 1);
        int t = idx >> 8;
        g_xT[idx] = x[(size_t)b * RT + t];
    }
    if (idx < NM) g_bar[idx] = 0u;
}

__global__ void __launch_bounds__(NTH, 1)
rnn_mma_kernel(const float* __restrict__ whx,
               const float* __restrict__ whh,
               const float* __restrict__ bias_h) {
    extern __shared__ char smem[];
    const uint32_t sb = smem_u32(smem);
    const uint32_t swh = sb + SW_HI;
    const uint32_t swl = sb + SW_LO;
    const uint32_t sa = sb + SA_OFF;

    const int tid = threadIdx.x;
    const int wid = tid >> 5;
    const int lane = tid & 31;
    const int bid = blockIdx.x;
    const int m = bid >> 5;              // 0..3 batch group
    const int n = bid & 31;              // 0..31 j tile
    const int jg0 = n * NT;
    const int brow0 = m * MT;

    // whh slice -> resident SMEM, split hi/lo bf16, padded rows.
    for (int idx = tid; idx < NT * (RH / 2); idx += NTH) {
        int jl = idx >> 9;                  // /512
        int k2 = (idx & 511) * 2;
        float2 wv = *reinterpret_cast<const float2*>(
            &whh[(size_t)(jg0 + jl) * RH + k2]);
        __nv_bfloat16 h0 = __float2bfloat16(wv.x);
        __nv_bfloat16 l0 = __float2bfloat16(wv.x - __bfloat162float(h0));
        __nv_bfloat16 h1 = __float2bfloat16(wv.y);
        __nv_bfloat16 l1 = __float2bfloat16(wv.y - __bfloat162float(h1));
        uint32_t off = (uint32_t)jl * W_PITCH + (uint32_t)k2 * 2u;
        __nv_bfloat162 p2h; p2h.x = h0; p2h.y = h1;
        __nv_bfloat162 p2l; p2l.x = l0; p2l.y = l1;
        *reinterpret_cast<__nv_bfloat162*>(smem + SW_HI + off) = p2h;
        *reinterpret_cast<__nv_bfloat162*>(smem + SW_LO + off) = p2l;
    }

    // ldmatrix addresses. Warp wid owns k-slice [wid*16, wid*16+16) of a chunk.
    const uint32_t a_off = (uint32_t)(lane & 15) * A_PITCH +
                           (uint32_t)(lane >> 4) * 16u + (uint32_t)wid * 32u;
    const uint32_t b_row = (uint32_t)((lane & 7) + ((lane & 16) ? 8 : 0));
    const uint32_t b_off0 = b_row * W_PITCH + (uint32_t)((lane >> 3) & 1) * 16u;
    const uint32_t b_off1 = b_off0 + 16u * W_PITCH;

    // Reduction / epilogue constants: thread owns batch row (tid>>2),
    // j columns (tid&3)*8 .. +7.
    const int erow = tid >> 2;
    const int ecol = (tid & 3) * 8;
    float wx[8], bs[8];
#pragma unroll
    for (int i = 0; i < 8; ++i) {
        wx[i] = whx[jg0 + ecol + i];
        bs[i] = bias_h[jg0 + ecol + i];
    }
    // Partial-store base for this warp's D fragments.
    const int fr = lane >> 2;            // fragment row within m16 (and +8)
    const int fc = 2 * (lane & 3);       // fragment col within n8 (pair)

    __syncthreads();
    volatile unsigned int* barp = &g_bar[m];

    for (int t = 0; t < RT; ++t) {
        const __nv_bfloat16* hh = &g_hh[t & 1][(size_t)brow0 * RH];
        const __nv_bfloat16* hl = &g_hl[t & 1][(size_t)brow0 * RH];

        copy_chunk(sa, hh, hl, 0);
        asm volatile("cp.async.commit_group;" ::: "memory");
        copy_chunk(sa + A_BUF, hh, hl, 1);
        asm volatile("cp.async.commit_group;" ::: "memory");

        float xb = g_xT[t * RB + brow0 + erow];

        float acc[64];
#pragma unroll
        for (int i = 0; i < 64; ++i) acc[i] = 0.f;

#pragma unroll 1
        for (int c = 0; c < NCH; ++c) {
            if (c < NCH - 1) asm volatile("cp.async.wait_group 1;" ::: "memory");
            else             asm volatile("cp.async.wait_group 0;" ::: "memory");
            __syncthreads();

            const uint32_t ab = sa + (uint32_t)(c & 1) * A_BUF;
            // B fragments for this warp's k16 slice: all 32 j.
            uint32_t bh[8], bl[8];
            const uint32_t kb = (uint32_t)(c * KC + wid * 16) * 2u;
            ldsm4(swh + b_off0 + kb, bh);
            ldsm4(swh + b_off1 + kb, bh + 4);
            ldsm4(swl + b_off0 + kb, bl);
            ldsm4(swl + b_off1 + kb, bl + 4);
#pragma unroll
            for (int mt = 0; mt < 4; ++mt) {
                uint32_t ahi[4], alo[4];
                const uint32_t am = ab + a_off + (uint32_t)(mt * 16) * A_PITCH;
                ldsm4(am, ahi);
                ldsm4(am + A_SPLIT, alo);
#pragma unroll
                for (int nt = 0; nt < 4; ++nt) {
                    const int bb = (nt >> 1) * 4 + (nt & 1) * 2;
                    float* d = acc + (mt * 4 + nt) * 4;
                    mma_bf16(d, ahi, bh[bb], bh[bb + 1]);
                    mma_bf16(d, ahi, bl[bb], bl[bb + 1]);
                    mma_bf16(d, alo, bh[bb], bh[bb + 1]);
                }
            }
            __syncthreads();
            if (c + 2 < NCH) {
                copy_chunk(sa + (uint32_t)(c & 1) * A_BUF, hh, hl, c + 2);
                asm volatile("cp.async.commit_group;" ::: "memory");
            }
        }

        // Cross-warp reduction of 8 partial 64x32 tiles through SMEM.
        // (A staging is free to overwrite: loop's final sync has passed.)
        {
            char* wr = smem + SA_OFF + wid * RED_WARP;
#pragma unroll
            for (int mt = 0; mt < 4; ++mt) {
#pragma unroll
                for (int nt = 0; nt < 4; ++nt) {
                    const float* d = acc + (mt * 4 + nt) * 4;
                    int r = mt * 16 + fr;
                    int cw = nt * 8 + fc;
                    float2 v0; v0.x = d[0]; v0.y = d[1];
                    float2 v1; v1.x = d[2]; v1.y = d[3];
                    *reinterpret_cast<float2*>(wr + r * RED_PITCH + cw * 4) = v0;
                    *reinterpret_cast<float2*>(wr + (r + 8) * RED_PITCH + cw * 4) = v1;
                }
            }
        }
        __syncthreads();

        // Each thread sums its 8 output elements over the 8 partials.
        float sum[8];
#pragma unroll
        for (int i = 0; i < 8; ++i) sum[i] = 0.f;
        {
            const char* rr = smem + SA_OFF + erow * RED_PITCH + ecol * 4;
#pragma unroll
            for (int w = 0; w < 8; ++w) {
                const char* p = rr + w * RED_WARP;
#pragma unroll
                for (int q = 0; q < 4; ++q) {
                    float2 v = *reinterpret_cast<const float2*>(p + q * 8);
                    sum[2 * q] += v.x;
                    sum[2 * q + 1] += v.y;
                }
            }
        }

        // Epilogue: add input + bias, tanh, split hi/lo, coalesced store.
        const int ob = (t + 1) & 1;
        uint32_t phi[4], plo[4];
#pragma unroll
        for (int q = 0; q < 4; ++q) {
            float a = tanh_acc(sum[2 * q] + fmaf(xb, wx[2 * q], bs[2 * q]));
            float b = tanh_acc(sum[2 * q + 1] + fmaf(xb, wx[2 * q + 1], bs[2 * q + 1]));
            __nv_bfloat16 ah = __float2bfloat16(a);
            __nv_bfloat16 bh = __float2bfloat16(b);
            __nv_bfloat16 al = __float2bfloat16(a - __bfloat162float(ah));
            __nv_bfloat16 bl2 = __float2bfloat16(b - __bfloat162float(bh));
            __nv_bfloat162 ph; ph.x = ah; ph.y = bh;
            __nv_bfloat162 pl; pl.x = al; pl.y = bl2;
            phi[q] = *reinterpret_cast<uint32_t*>(&ph);
            plo[q] = *reinterpret_cast<uint32_t*>(&pl);
        }
        {
            size_t po = (size_t)(brow0 + erow) * RH + jg0 + ecol;
            uint4 uh; uh.x = phi[0]; uh.y = phi[1]; uh.z = phi[2]; uh.w = phi[3];
            uint4 ul; ul.x = plo[0]; ul.y = plo[1]; ul.z = plo[2]; ul.w = plo[3];
            *reinterpret_cast<uint4*>(&g_hh[ob][po]) = uh;
            *reinterpret_cast<uint4*>(&g_hl[ob][po]) = ul;
        }

        // Per-group barrier (32 CTAs), monotonic counter reset by init kernel.
        __threadfence();
        __syncthreads();
        if (tid == 0) {
            atomicAdd(&g_bar[m], 1u);
            unsigned int target = (unsigned int)(t + 1) * NN;
            while (*barp < target) { }
            __threadfence();
        }
        __syncthreads();
    }
}

// p[b][c] = (h_hi + h_lo)[b] . wph[c] + bias_p[c]; final h is in buffer 0.
__global__ void __launch_bounds__(RB, 1)
rnn_proj_kernel(const float* __restrict__ wph,
                const float* __restrict__ bias_p,
                float* __restrict__ out) {
    const int c = blockIdx.x;    // 0..9
    const int b = threadIdx.x;   // 0..255
    const __nv_bfloat16* hh = &g_hh[0][(size_t)b * RH];
    const __nv_bfloat16* hl = &g_hl[0][(size_t)b * RH];
    const float* w = wph + (size_t)c * RH;
    float a0 = 0.0f, a1 = 0.0f;
#pragma unroll 4
    for (int k = 0; k < RH; k += 2) {
        __nv_bfloat162 h2 = *reinterpret_cast<const __nv_bfloat162*>(hh + k);
        __nv_bfloat162 l2 = *reinterpret_cast<const __nv_bfloat162*>(hl + k);
        a0 = fmaf(__bfloat162float(h2.x) + __bfloat162float(l2.x), w[k], a0);
        a1 = fmaf(__bfloat162float(h2.y) + __bfloat162float(l2.y), w[k + 1], a1);
    }
    out[b * RC + c] = a0 + a1 + bias_p[c];
}

extern "C" void kernel_launch(void* const* d_in, const int* in_sizes, int n_in,
                              void* d_out, int out_size) {
    (void)in_sizes; (void)n_in; (void)out_size;
    const float* x      = (const float*)d_in[0];   // [B, T]
    const float* whx    = (const float*)d_in[1];   // [H, 1]
    const float* whh    = (const float*)d_in[2];   // [H, H]
    const float* bias_h = (const float*)d_in[3];   // [H]
    const float* wph    = (const float*)d_in[4];   // [C, H]
    const float* bias_p = (const float*)d_in[5];   // [C]
    float* out = (float*)d_out;                    // [B, C]

    cudaFuncSetAttribute(rnn_mma_kernel,
                         cudaFuncAttributeMaxDynamicSharedMemorySize, SMEM_BYTES);

    rnn_init_kernel<<<(RB * RH + NTH - 1) / NTH, NTH>>>(x);
    rnn_mma_kernel<<<NM * NN, NTH, SMEM_BYTES>>>(whx, whh, bias_h);
    rnn_proj_kernel<<<RC, RB>>>(wph, bias_p, out);
}

// round 11
// speedup vs baseline: 2.0452x; 1.7924x over previous
#include <cuda_runtime.h>
#include <cuda_fp16.h>
#include <math.h>
#include <stdint.h>

// Problem constants
#define RB 256      // batch
#define RT 512      // time steps
#define RH 1024     // hidden
#define RC 10       // classes

// Tiling: 4 batch groups (M=64) x 32 j-tiles (N=32) = 128 CTAs (1 per SM)
#define NM 4
#define NN 32
#define MT 64
#define NT 32
#define KC 256             // k per staged chunk
#define NCH 4              // chunks per step
#define NTH 256            // 8 warps, each owns a k32 slice of a chunk

// SMEM byte layout (dynamic)
// W rows padded to 2064B (1032 fp16) for conflict-free ldmatrix (8-row stride)
#define W_PITCH 2064
#define SW_OFF 0                         // 32 rows x 2064 = 66048
#define SA_OFF 66048
// A chunk: 64 rows x 528B (256 fp16 data + 16B pad)
#define A_PITCH 528
#define A_BUF 33792                      // one chunk
// Reduction scratch overlaps A staging: 8 warps x 64 rows x 144B = 73728
#define RED_PITCH 144
#define RED_WARP (64 * RED_PITCH)        // 9216
#define SMEM_BYTES (SA_OFF + 73728)      // 139776

// Persistent state (device globals; no allocation)
__device__ __half g_h[2][RB * RH];           // hidden state fp16, [b][k]
__device__ float g_xT[RT * RB];              // x transposed: [t][b]
__device__ unsigned int g_bar[NM];           // per-group monotonic barrier

// ----------------- helpers -----------------
__device__ __forceinline__ uint32_t smem_u32(const void* p) {
    uint32_t a;
    asm("{ .reg .u64 t; cvta.to.shared.u64 t, %1; cvt.u32.u64 %0, t; }"
        : "=r"(a) : "l"(p));
    return a;
}

__device__ __forceinline__ void ldsm4(uint32_t addr, uint32_t r[4]) {
    asm volatile("ldmatrix.sync.aligned.m8n8.x4.shared.b16 {%0,%1,%2,%3}, [%4];"
                 : "=r"(r[0]), "=r"(r[1]), "=r"(r[2]), "=r"(r[3]) : "r"(addr));
}

__device__ __forceinline__ void mma_f16(float* d, const uint32_t a[4],
                                        uint32_t b0, uint32_t b1) {
    asm volatile(
        "mma.sync.aligned.m16n8k16.row.col.f32.f16.f16.f32 "
        "{%0,%1,%2,%3},{%4,%5,%6,%7},{%8,%9},{%0,%1,%2,%3};"
        : "+f"(d[0]), "+f"(d[1]), "+f"(d[2]), "+f"(d[3])
        : "r"(a[0]), "r"(a[1]), "r"(a[2]), "r"(a[3]), "r"(b0), "r"(b1));
}

__device__ __forceinline__ void cp16(uint32_t d, const void* s) {
    asm volatile("cp.async.cg.shared.global [%0], [%1], 16;"
                 :: "r"(d), "l"(s) : "memory");
}

__device__ __forceinline__ uint32_t ld_acq(const unsigned int* p) {
    uint32_t v;
    asm volatile("ld.acquire.gpu.global.u32 %0, [%1];" : "=r"(v) : "l"(p)
                 : "memory");
    return v;
}
__device__ __forceinline__ void red_rel_add1(unsigned int* p) {
    asm volatile("red.release.gpu.global.add.u32 [%0], %1;"
                 :: "l"(p), "r"(1u) : "memory");
}

// Accurate tanh independent of fast-math lowering.
__device__ __forceinline__ float tanh_acc(float v) {
    float ax = fabsf(v);
    if (ax < 0.25f) {
        float s = v * v;
        float p = fmaf(s, 0.021869488f, -0.05396825397f);
        p = fmaf(s, p, 0.13333333333f);
        p = fmaf(s, p, -0.33333333333f);
        return fmaf(v * s, p, v);
    } else {
        float e = expf(-2.0f * ax);
        float r = (1.0f - e) / (1.0f + e);
        return copysignf(r, v);
    }
}

// Stage one 64x256 fp16 chunk into a padded A buffer.
__device__ __forceinline__ void copy_chunk(uint32_t abuf,
                                           const __half* __restrict__ h,
                                           int chunk) {
    const int tid = threadIdx.x;
    const __half* s = h + chunk * KC;
#pragma unroll
    for (int i = 0; i < 8; ++i) {
        int seg = tid + i * NTH;            // 0..2047: 16B segments
        int row = seg >> 5;                 // 32 segs per 512B row
        int c16 = seg & 31;
        uint32_t doff = (uint32_t)row * A_PITCH + (uint32_t)c16 * 16u;
        const char* gs = (const char*)(s + (size_t)row * RH) + c16 * 16;
        cp16(abuf + doff, gs);
    }
}

__global__ void __launch_bounds__(NTH, 1)
rnn_init_kernel(const float* __restrict__ x) {
    int idx = blockIdx.x * blockDim.x + threadIdx.x;
    if (idx < RB * RH) g_h[0][idx] = __float2half(0.0f);
    if (idx < RT * RB) {
        int b = idx & (RB - 1);
        int t = idx >> 8;
        g_xT[idx] = x[(size_t)b * RT + t];
    }
    if (idx < NM) g_bar[idx] = 0u;
}

__global__ void __launch_bounds__(NTH, 1)
rnn_mma_kernel(const float* __restrict__ whx,
               const float* __restrict__ whh,
               const float* __restrict__ bias_h) {
    extern __shared__ char smem[];
    const uint32_t sb = smem_u32(smem);
    const uint32_t sw = sb + SW_OFF;
    const uint32_t sa = sb + SA_OFF;

    const int tid = threadIdx.x;
    const int wid = tid >> 5;
    const int lane = tid & 31;
    const int bid = blockIdx.x;
    const int m = bid >> 5;              // 0..3 batch group
    const int n = bid & 31;              // 0..31 j tile
    const int jg0 = n * NT;
    const int brow0 = m * MT;

    // whh slice -> resident SMEM fp16, padded rows.
    for (int idx = tid; idx < NT * (RH / 2); idx += NTH) {
        int jl = idx >> 9;                  // /512
        int k2 = (idx & 511) * 2;
        float2 wv = *reinterpret_cast<const float2*>(
            &whh[(size_t)(jg0 + jl) * RH + k2]);
        __half2 p2;
        p2.x = __float2half(wv.x);
        p2.y = __float2half(wv.y);
        uint32_t off = (uint32_t)jl * W_PITCH + (uint32_t)k2 * 2u;
        *reinterpret_cast<__half2*>(smem + SW_OFF + off) = p2;
    }

    // ldmatrix addresses. Warp wid owns k-slices {2*wid, 2*wid+1} (k16 each).
    const uint32_t a_off = (uint32_t)(lane & 15) * A_PITCH +
                           (uint32_t)(lane >> 4) * 16u + (uint32_t)wid * 64u;
    const uint32_t b_row = (uint32_t)((lane & 7) + ((lane & 16) ? 8 : 0));
    const uint32_t b_off0 = b_row * W_PITCH + (uint32_t)((lane >> 3) & 1) * 16u;
    const uint32_t b_off1 = b_off0 + 16u * W_PITCH;

    // Reduction / epilogue constants: thread owns batch row (tid>>2),
    // j columns (tid&3)*8 .. +7.
    const int erow = tid >> 2;
    const int ecol = (tid & 3) * 8;
    float wx[8], bs[8];
#pragma unroll
    for (int i = 0; i < 8; ++i) {
        wx[i] = whx[jg0 + ecol + i];
        bs[i] = bias_h[jg0 + ecol + i];
    }
    const int fr = lane >> 2;            // fragment row within m16 (and +8)
    const int fc = 2 * (lane & 3);       // fragment col within n8 (pair)

    __syncthreads();

    for (int t = 0; t < RT; ++t) {
        const __half* h = &g_h[t & 1][(size_t)brow0 * RH];

        copy_chunk(sa, h, 0);
        asm volatile("cp.async.commit_group;" ::: "memory");
        copy_chunk(sa + A_BUF, h, 1);
        asm volatile("cp.async.commit_group;" ::: "memory");

        float xb = g_xT[t * RB + brow0 + erow];

        float acc[64];
#pragma unroll
        for (int i = 0; i < 64; ++i) acc[i] = 0.f;

#pragma unroll 1
        for (int c = 0; c < NCH; ++c) {
            if (c < NCH - 1) asm volatile("cp.async.wait_group 1;" ::: "memory");
            else             asm volatile("cp.async.wait_group 0;" ::: "memory");
            __syncthreads();

            const uint32_t ab = sa + (uint32_t)(c & 1) * A_BUF;
#pragma unroll
            for (int s = 0; s < 2; ++s) {
                // B fragments for this k16 slice: all 32 j.
                uint32_t bf[8];
                const uint32_t kb =
                    (uint32_t)(c * KC + (wid * 2 + s) * 16) * 2u;
                ldsm4(sw + b_off0 + kb, bf);
                ldsm4(sw + b_off1 + kb, bf + 4);
#pragma unroll
                for (int mt = 0; mt < 4; ++mt) {
                    uint32_t af[4];
                    ldsm4(ab + a_off + (uint32_t)(mt * 16) * A_PITCH +
                          (uint32_t)s * 32u, af);
#pragma unroll
                    for (int nt = 0; nt < 4; ++nt) {
                        const int bb = (nt >> 1) * 4 + (nt & 1) * 2;
                        mma_f16(acc + (mt * 4 + nt) * 4, af, bf[bb], bf[bb + 1]);
                    }
                }
            }
            __syncthreads();
            if (c + 2 < NCH) {
                copy_chunk(sa + (uint32_t)(c & 1) * A_BUF, h, c + 2);
                asm volatile("cp.async.commit_group;" ::: "memory");
            }
        }

        // Cross-warp reduction of 8 partial 64x32 tiles through SMEM.
        {
            char* wr = smem + SA_OFF + wid * RED_WARP;
#pragma unroll
            for (int mt = 0; mt < 4; ++mt) {
#pragma unroll
                for (int nt = 0; nt < 4; ++nt) {
                    const float* d = acc + (mt * 4 + nt) * 4;
                    int r = mt * 16 + fr;
                    int cw = nt * 8 + fc;
                    float2 v0; v0.x = d[0]; v0.y = d[1];
                    float2 v1; v1.x = d[2]; v1.y = d[3];
                    *reinterpret_cast<float2*>(wr + r * RED_PITCH + cw * 4) = v0;
                    *reinterpret_cast<float2*>(wr + (r + 8) * RED_PITCH + cw * 4) = v1;
                }
            }
        }
        __syncthreads();

        // Each thread sums its 8 output elements over the 8 partials.
        float sum[8];
#pragma unroll
        for (int i = 0; i < 8; ++i) sum[i] = 0.f;
        {
            const char* rr = smem + SA_OFF + erow * RED_PITCH + ecol * 4;
#pragma unroll
            for (int w = 0; w < 8; ++w) {
                const char* p = rr + w * RED_WARP;
#pragma unroll
                for (int q = 0; q < 4; ++q) {
                    float2 v = *reinterpret_cast<const float2*>(p + q * 8);
                    sum[2 * q] += v.x;
                    sum[2 * q + 1] += v.y;
                }
            }
        }

        // Epilogue: add input + bias, tanh, fp16 store (coalesced 16B).
        const int ob = (t + 1) & 1;
        uint32_t pk[4];
#pragma unroll
        for (int q = 0; q < 4; ++q) {
            float a = tanh_acc(sum[2 * q] + fmaf(xb, wx[2 * q], bs[2 * q]));
            float b = tanh_acc(sum[2 * q + 1] + fmaf(xb, wx[2 * q + 1], bs[2 * q + 1]));
            __half2 p2;
            p2.x = __float2half(a);
            p2.y = __float2half(b);
            pk[q] = *reinterpret_cast<uint32_t*>(&p2);
        }
        {
            size_t po = (size_t)(brow0 + erow) * RH + jg0 + ecol;
            uint4 u; u.x = pk[0]; u.y = pk[1]; u.z = pk[2]; u.w = pk[3];
            *reinterpret_cast<uint4*>(&g_h[ob][po]) = u;
        }

        // Per-group barrier (32 CTAs): release-add + acquire-poll (cg pattern).
        __syncthreads();
        if (tid == 0) {
            red_rel_add1(&g_bar[m]);
            unsigned int target = (unsigned int)(t + 1) * NN;
            while (ld_acq(&g_bar[m]) < target) { }
        }
        __syncthreads();
    }
}

// p[b][c] = h_final[b] . wph[c] + bias_p[c]; final h is in buffer 0 (RT even).
__global__ void __launch_bounds__(RB, 1)
rnn_proj_kernel(const float* __restrict__ wph,
                const float* __restrict__ bias_p,
                float* __restrict__ out) {
    const int c = blockIdx.x;    // 0..9
    const int b = threadIdx.x;   // 0..255
    const __half* h = &g_h[0][(size_t)b * RH];
    const float* w = wph + (size_t)c * RH;
    float a0 = 0.0f, a1 = 0.0f;
#pragma unroll 4
    for (int k = 0; k < RH; k += 2) {
        __half2 h2 = *reinterpret_cast<const __half2*>(h + k);
        a0 = fmaf(__half2float(h2.x), w[k], a0);
        a1 = fmaf(__half2float(h2.y), w[k + 1], a1);
    }
    out[b * RC + c] = a0 + a1 + bias_p[c];
}

extern "C" void kernel_launch(void* const* d_in, const int* in_sizes, int n_in,
                              void* d_out, int out_size) {
    (void)in_sizes; (void)n_in; (void)out_size;
    const float* x      = (const float*)d_in[0];   // [B, T]
    const float* whx    = (const float*)d_in[1];   // [H, 1]
    const float* whh    = (const float*)d_in[2];   // [H, H]
    const float* bias_h = (const float*)d_in[3];   // [H]
    const float* wph    = (const float*)d_in[4];   // [C, H]
    const float* bias_p = (const float*)d_in[5];   // [C]
    float* out = (float*)d_out;                    // [B, C]

    cudaFuncSetAttribute(rnn_mma_kernel,
                         cudaFuncAttributeMaxDynamicSharedMemorySize, SMEM_BYTES);

    rnn_init_kernel<<<(RB * RH + NTH - 1) / NTH, NTH>>>(x);
    rnn_mma_kernel<<<NM * NN, NTH, SMEM_BYTES>>>(whx, whh, bias_h);
    rnn_proj_kernel<<<RC, RB>>>(wph, bias_p, out);
}

// round 12
// speedup vs baseline: 2.5353x; 1.2396x over previous
#include <cuda_runtime.h>
#include <cuda_fp16.h>
#include <math.h>
#include <stdint.h>

// Problem constants
#define RB 256      // batch
#define RT 512      // time steps
#define RH 1024     // hidden
#define RC 10       // classes

// Tiling: 8 batch groups (M=32) x 16 j-tiles (N=64) = 128 CTAs (1 per SM)
#define NM 8
#define NN 16
#define MT 32
#define NT 64
#define KCH 512            // k per staged chunk
#define NCH 2              // chunks per step
#define NTH 256            // 8 warps, each owns a k64 slice of each chunk

// SMEM byte layout (dynamic)
// W rows padded to 2064B (1032 fp16) for conflict-free ldmatrix (8-row stride)
#define W_PITCH 2064
#define SW_OFF 0                          // 64 rows x 2064 = 132096
#define SA_OFF 132096
// A chunk: 32 rows x 1040B (512 fp16 data + 16B pad)
#define A_PITCH 1040
#define A_BUF 33280                       // one chunk
// Reduction scratch overlaps A staging: 8 warps x 32 rows x 272B = 69632
#define RED_PITCH 272
#define RED_WARP (32 * RED_PITCH)         // 8704
#define SMEM_BYTES (SA_OFF + 69632)       // 201728

// Persistent state (device globals; no allocation)
__device__ __half g_h[2][RB * RH];           // hidden state fp16, [b][k]
__device__ float g_xT[RT * RB];              // x transposed: [t][b]
__device__ unsigned int g_bar[NM];           // per-group monotonic barrier

// ----------------- helpers -----------------
__device__ __forceinline__ uint32_t smem_u32(const void* p) {
    uint32_t a;
    asm("{ .reg .u64 t; cvta.to.shared.u64 t, %1; cvt.u32.u64 %0, t; }"
        : "=r"(a) : "l"(p));
    return a;
}

__device__ __forceinline__ void ldsm4(uint32_t addr, uint32_t r[4]) {
    asm volatile("ldmatrix.sync.aligned.m8n8.x4.shared.b16 {%0,%1,%2,%3}, [%4];"
                 : "=r"(r[0]), "=r"(r[1]), "=r"(r[2]), "=r"(r[3]) : "r"(addr));
}

__device__ __forceinline__ void mma_f16(float* d, const uint32_t a[4],
                                        uint32_t b0, uint32_t b1) {
    asm volatile(
        "mma.sync.aligned.m16n8k16.row.col.f32.f16.f16.f32 "
        "{%0,%1,%2,%3},{%4,%5,%6,%7},{%8,%9},{%0,%1,%2,%3};"
        : "+f"(d[0]), "+f"(d[1]), "+f"(d[2]), "+f"(d[3])
        : "r"(a[0]), "r"(a[1]), "r"(a[2]), "r"(a[3]), "r"(b0), "r"(b1));
}

__device__ __forceinline__ void cp16(uint32_t d, const void* s) {
    asm volatile("cp.async.cg.shared.global [%0], [%1], 16;"
                 :: "r"(d), "l"(s) : "memory");
}

__device__ __forceinline__ uint32_t ld_acq(const unsigned int* p) {
    uint32_t v;
    asm volatile("ld.acquire.gpu.global.u32 %0, [%1];" : "=r"(v) : "l"(p)
                 : "memory");
    return v;
}
__device__ __forceinline__ void red_rel_add1(unsigned int* p) {
    asm volatile("red.release.gpu.global.add.u32 [%0], %1;"
                 :: "l"(p), "r"(1u) : "memory");
}

// Accurate tanh independent of fast-math lowering.
__device__ __forceinline__ float tanh_acc(float v) {
    float ax = fabsf(v);
    if (ax < 0.25f) {
        float s = v * v;
        float p = fmaf(s, 0.021869488f, -0.05396825397f);
        p = fmaf(s, p, 0.13333333333f);
        p = fmaf(s, p, -0.33333333333f);
        return fmaf(v * s, p, v);
    } else {
        float e = expf(-2.0f * ax);
        float r = (1.0f - e) / (1.0f + e);
        return copysignf(r, v);
    }
}

// Stage one 32x512 fp16 chunk into a padded A buffer.
__device__ __forceinline__ void copy_chunk(uint32_t abuf,
                                           const __half* __restrict__ h,
                                           int chunk) {
    const int tid = threadIdx.x;
    const __half* s = h + chunk * KCH;
#pragma unroll
    for (int i = 0; i < 8; ++i) {
        int seg = tid + i * NTH;            // 0..2047: 16B segments
        int row = seg >> 6;                 // 64 segs per 1024B row
        int c16 = seg & 63;
        uint32_t doff = (uint32_t)row * A_PITCH + (uint32_t)c16 * 16u;
        const char* gs = (const char*)(s + (size_t)row * RH) + c16 * 16;
        cp16(abuf + doff, gs);
    }
}

__global__ void __launch_bounds__(NTH, 1)
rnn_init_kernel(const float* __restrict__ x) {
    int idx = blockIdx.x * blockDim.x + threadIdx.x;
    if (idx < RB * RH) g_h[0][idx] = __float2half(0.0f);
    if (idx < RT * RB) {
        int b = idx & (RB - 1);
        int t = idx >> 8;
        g_xT[idx] = x[(size_t)b * RT + t];
    }
    if (idx < NM) g_bar[idx] = 0u;
}

__global__ void __launch_bounds__(NTH, 1)
rnn_mma_kernel(const float* __restrict__ whx,
               const float* __restrict__ whh,
               const float* __restrict__ bias_h) {
    extern __shared__ char smem[];
    const uint32_t sb = smem_u32(smem);
    const uint32_t sw = sb + SW_OFF;
    const uint32_t sa = sb + SA_OFF;

    const int tid = threadIdx.x;
    const int wid = tid >> 5;
    const int lane = tid & 31;
    const int bid = blockIdx.x;
    const int m = bid >> 4;              // 0..7 batch group
    const int n = bid & 15;              // 0..15 j tile
    const int jg0 = n * NT;
    const int brow0 = m * MT;

    // whh slice (64 j rows x 1024 k) -> resident SMEM fp16, padded rows.
    for (int idx = tid; idx < NT * (RH / 2); idx += NTH) {
        int jl = idx >> 9;                  // /512
        int k2 = (idx & 511) * 2;
        float2 wv = *reinterpret_cast<const float2*>(
            &whh[(size_t)(jg0 + jl) * RH + k2]);
        __half2 p2;
        p2.x = __float2half(wv.x);
        p2.y = __float2half(wv.y);
        uint32_t off = (uint32_t)jl * W_PITCH + (uint32_t)k2 * 2u;
        *reinterpret_cast<__half2*>(smem + SW_OFF + off) = p2;
    }

    // ldmatrix addresses. Warp wid owns k-slice [wid*64, wid*64+64) per chunk.
    const uint32_t a_off = (uint32_t)(lane & 15) * A_PITCH +
                           (uint32_t)(lane >> 4) * 16u + (uint32_t)wid * 128u;
    const uint32_t b_row = (uint32_t)((lane & 7) + ((lane & 16) ? 8 : 0));
    const uint32_t b_base = b_row * W_PITCH + (uint32_t)((lane >> 3) & 1) * 16u;

    // Reduction / epilogue constants: thread owns batch row (tid>>3),
    // j columns (tid&7)*8 .. +7.
    const int erow = tid >> 3;
    const int ecol = (tid & 7) * 8;
    float wx[8], bs[8];
#pragma unroll
    for (int i = 0; i < 8; ++i) {
        wx[i] = whx[jg0 + ecol + i];
        bs[i] = bias_h[jg0 + ecol + i];
    }
    const int fr = lane >> 2;            // fragment row within m16 (and +8)
    const int fc = 2 * (lane & 3);       // fragment col within n8 (pair)

    __syncthreads();

    for (int t = 0; t < RT; ++t) {
        const __half* h = &g_h[t & 1][(size_t)brow0 * RH];

        copy_chunk(sa, h, 0);
        asm volatile("cp.async.commit_group;" ::: "memory");
        copy_chunk(sa + A_BUF, h, 1);
        asm volatile("cp.async.commit_group;" ::: "memory");

        float xb = g_xT[t * RB + brow0 + erow];

        float acc[64];
#pragma unroll
        for (int i = 0; i < 64; ++i) acc[i] = 0.f;

#pragma unroll
        for (int c = 0; c < NCH; ++c) {
            if (c == 0) asm volatile("cp.async.wait_group 1;" ::: "memory");
            else        asm volatile("cp.async.wait_group 0;" ::: "memory");
            __syncthreads();

            const uint32_t ab = sa + (uint32_t)c * A_BUF;
#pragma unroll
            for (int s = 0; s < 4; ++s) {
                // B fragments for this k16 slice: all 64 j.
                uint32_t bf[16];
                const uint32_t kb =
                    (uint32_t)(c * KCH + wid * 64 + s * 16) * 2u;
#pragma unroll
                for (int q = 0; q < 4; ++q)
                    ldsm4(sw + b_base + (uint32_t)(q * 16) * W_PITCH + kb,
                          bf + q * 4);
#pragma unroll
                for (int mt = 0; mt < 2; ++mt) {
                    uint32_t af[4];
                    ldsm4(ab + a_off + (uint32_t)(mt * 16) * A_PITCH +
                          (uint32_t)s * 32u, af);
#pragma unroll
                    for (int nt = 0; nt < 8; ++nt) {
                        const int bb = (nt >> 1) * 4 + (nt & 1) * 2;
                        mma_f16(acc + (mt * 8 + nt) * 4, af, bf[bb], bf[bb + 1]);
                    }
                }
            }
            __syncthreads();
        }

        // Cross-warp reduction of 8 partial 32x64 tiles through SMEM
        // (A staging is dead now; scratch overlaps it).
        {
            char* wr = smem + SA_OFF + wid * RED_WARP;
#pragma unroll
            for (int mt = 0; mt < 2; ++mt) {
#pragma unroll
                for (int nt = 0; nt < 8; ++nt) {
                    const float* d = acc + (mt * 8 + nt) * 4;
                    int r = mt * 16 + fr;
                    int cw = nt * 8 + fc;
                    float2 v0; v0.x = d[0]; v0.y = d[1];
                    float2 v1; v1.x = d[2]; v1.y = d[3];
                    *reinterpret_cast<float2*>(wr + r * RED_PITCH + cw * 4) = v0;
                    *reinterpret_cast<float2*>(wr + (r + 8) * RED_PITCH + cw * 4) = v1;
                }
            }
        }
        __syncthreads();

        // Each thread sums its 8 output elements over the 8 partials.
        float sum[8];
#pragma unroll
        for (int i = 0; i < 8; ++i) sum[i] = 0.f;
        {
            const char* rr = smem + SA_OFF + erow * RED_PITCH + ecol * 4;
#pragma unroll
            for (int w = 0; w < 8; ++w) {
                const char* p = rr + w * RED_WARP;
#pragma unroll
                for (int q = 0; q < 4; ++q) {
                    float2 v = *reinterpret_cast<const float2*>(p + q * 8);
                    sum[2 * q] += v.x;
                    sum[2 * q + 1] += v.y;
                }
            }
        }

        // Epilogue: add input + bias, tanh, fp16 store (coalesced 16B).
        const int ob = (t + 1) & 1;
        uint32_t pk[4];
#pragma unroll
        for (int q = 0; q < 4; ++q) {
            float a = tanh_acc(sum[2 * q] + fmaf(xb, wx[2 * q], bs[2 * q]));
            float b = tanh_acc(sum[2 * q + 1] + fmaf(xb, wx[2 * q + 1], bs[2 * q + 1]));
            __half2 p2;
            p2.x = __float2half(a);
            p2.y = __float2half(b);
            pk[q] = *reinterpret_cast<uint32_t*>(&p2);
        }
        {
            size_t po = (size_t)(brow0 + erow) * RH + jg0 + ecol;
            uint4 u; u.x = pk[0]; u.y = pk[1]; u.z = pk[2]; u.w = pk[3];
            *reinterpret_cast<uint4*>(&g_h[ob][po]) = u;
        }

        // Per-group barrier (16 CTAs): release-add + acquire-poll.
        __syncthreads();
        if (tid == 0) {
            red_rel_add1(&g_bar[m]);
            unsigned int target = (unsigned int)(t + 1) * NN;
            while (ld_acq(&g_bar[m]) < target) { }
        }
        __syncthreads();
    }
}

// p[b][c] = h_final[b] . wph[c] + bias_p[c]; final h is in buffer 0 (RT even).
__global__ void __launch_bounds__(RB, 1)
rnn_proj_kernel(const float* __restrict__ wph,
                const float* __restrict__ bias_p,
                float* __restrict__ out) {
    const int c = blockIdx.x;    // 0..9
    const int b = threadIdx.x;   // 0..255
    const __half* h = &g_h[0][(size_t)b * RH];
    const float* w = wph + (size_t)c * RH;
    float a0 = 0.0f, a1 = 0.0f;
#pragma unroll 4
    for (int k = 0; k < RH; k += 2) {
        __half2 h2 = *reinterpret_cast<const __half2*>(h + k);
        a0 = fmaf(__half2float(h2.x), w[k], a0);
        a1 = fmaf(__half2float(h2.y), w[k + 1], a1);
    }
    out[b * RC + c] = a0 + a1 + bias_p[c];
}

extern "C" void kernel_launch(void* const* d_in, const int* in_sizes, int n_in,
                              void* d_out, int out_size) {
    (void)in_sizes; (void)n_in; (void)out_size;
    const float* x      = (const float*)d_in[0];   // [B, T]
    const float* whx    = (const float*)d_in[1];   // [H, 1]
    const float* whh    = (const float*)d_in[2];   // [H, H]
    const float* bias_h = (const float*)d_in[3];   // [H]
    const float* wph    = (const float*)d_in[4];   // [C, H]
    const float* bias_p = (const float*)d_in[5];   // [C]
    float* out = (float*)d_out;                    // [B, C]

    cudaFuncSetAttribute(rnn_mma_kernel,
                         cudaFuncAttributeMaxDynamicSharedMemorySize, SMEM_BYTES);

    rnn_init_kernel<<<(RB * RH + NTH - 1) / NTH, NTH>>>(x);
    rnn_mma_kernel<<<NM * NN, NTH, SMEM_BYTES>>>(whx, whh, bias_h);
    rnn_proj_kernel<<<RC, RB>>>(wph, bias_p, out);
}

// round 13
// speedup vs baseline: 2.6629x; 1.0503x over previous
#include <cuda_runtime.h>
#include <cuda_fp16.h>
#include <math.h>
#include <stdint.h>

// Problem constants
#define RB 256      // batch
#define RT 512      // time steps
#define RH 1024     // hidden
#define RC 10       // classes

// Tiling: 8 batch groups (M=32) x 16 j-tiles (N=64) = 128 CTAs (1 per SM)
#define NM 8
#define NN 16
#define MT 32
#define NT 64
#define KH 512             // k per half (one chunk per warp-group)
#define NTH 256            // 8 warps: (half = wid>>2, nq = wid&3)

// SMEM byte layout (dynamic)
#define W_PITCH 2064
#define SW_OFF 0                          // 64 rows x 2064 = 132096
#define SA_OFF 132096
// A chunk: 32 rows x 1040B (512 fp16 data + 16B pad)
#define A_PITCH 1040
#define A_BUF 33280                       // one chunk (one per half)
#define SR_OFF (SA_OFF + 2 * A_BUF)       // 198656: reduction scratch
#define R_PITCH 80                        // 16 floats + 16B pad
#define R_TILE (32 * R_PITCH + 32)        // 2592 (stagger tiles by 32B)
#define SMEM_BYTES (SR_OFF + 8 * R_TILE)  // 219392

// Persistent state (device globals; no allocation)
__device__ __half g_h[2][RB * RH];           // hidden state fp16, [b][k]
__device__ float g_xT[RT * RB];              // x transposed: [t][b]
__device__ unsigned int g_cnt[NM][2][32];    // per-(group, k-half) counters

// ----------------- helpers -----------------
__device__ __forceinline__ uint32_t smem_u32(const void* p) {
    uint32_t a;
    asm("{ .reg .u64 t; cvta.to.shared.u64 t, %1; cvt.u32.u64 %0, t; }"
        : "=r"(a) : "l"(p));
    return a;
}

__device__ __forceinline__ void ldsm4(uint32_t addr, uint32_t r[4]) {
    asm volatile("ldmatrix.sync.aligned.m8n8.x4.shared.b16 {%0,%1,%2,%3}, [%4];"
                 : "=r"(r[0]), "=r"(r[1]), "=r"(r[2]), "=r"(r[3]) : "r"(addr));
}

__device__ __forceinline__ void mma_f16(float* d, const uint32_t a[4],
                                        uint32_t b0, uint32_t b1) {
    asm volatile(
        "mma.sync.aligned.m16n8k16.row.col.f32.f16.f16.f32 "
        "{%0,%1,%2,%3},{%4,%5,%6,%7},{%8,%9},{%0,%1,%2,%3};"
        : "+f"(d[0]), "+f"(d[1]), "+f"(d[2]), "+f"(d[3])
        : "r"(a[0]), "r"(a[1]), "r"(a[2]), "r"(a[3]), "r"(b0), "r"(b1));
}

__device__ __forceinline__ void cp16(uint32_t d, const void* s) {
    asm volatile("cp.async.cg.shared.global [%0], [%1], 16;"
                 :: "r"(d), "l"(s) : "memory");
}

__device__ __forceinline__ uint32_t ld_acq(const unsigned int* p) {
    uint32_t v;
    asm volatile("ld.acquire.gpu.global.u32 %0, [%1];" : "=r"(v) : "l"(p)
                 : "memory");
    return v;
}
__device__ __forceinline__ void red_rel_add1(unsigned int* p) {
    asm volatile("red.release.gpu.global.add.u32 [%0], %1;"
                 :: "l"(p), "r"(1u) : "memory");
}
__device__ __forceinline__ void bar_sync(int id) {
    asm volatile("bar.sync %0, 128;" :: "r"(id) : "memory");
}

// Accurate tanh independent of fast-math lowering.
__device__ __forceinline__ float tanh_acc(float v) {
    float ax = fabsf(v);
    if (ax < 0.25f) {
        float s = v * v;
        float p = fmaf(s, 0.021869488f, -0.05396825397f);
        p = fmaf(s, p, 0.13333333333f);
        p = fmaf(s, p, -0.33333333333f);
        return fmaf(v * s, p, v);
    } else {
        float e = expf(-2.0f * ax);
        float r = (1.0f - e) / (1.0f + e);
        return copysignf(r, v);
    }
}

__global__ void __launch_bounds__(NTH, 1)
rnn_init_kernel(const float* __restrict__ x) {
    int idx = blockIdx.x * blockDim.x + threadIdx.x;
    if (idx < RB * RH) g_h[0][idx] = __float2half(0.0f);
    if (idx < RT * RB) {
        int b = idx & (RB - 1);
        int t = idx >> 8;
        g_xT[idx] = x[(size_t)b * RT + t];
    }
    if (idx < NM * 2 * 32) ((unsigned int*)g_cnt)[idx] = 0u;
}

__global__ void __launch_bounds__(NTH, 1)
rnn_mma_kernel(const float* __restrict__ whx,
               const float* __restrict__ whh,
               const float* __restrict__ bias_h) {
    extern __shared__ char smem[];
    const uint32_t sb = smem_u32(smem);
    const uint32_t sw = sb + SW_OFF;

    const int tid = threadIdx.x;
    const int wid = tid >> 5;
    const int lane = tid & 31;
    const int lt = tid & 127;            // thread id within warp-group
    const int bid = blockIdx.x;
    const int m = bid >> 4;              // 0..7 batch group
    const int n = bid & 15;              // 0..15 j tile
    const int jg0 = n * NT;
    const int brow0 = m * MT;

    const int half = wid >> 2;           // 0..1 k-half (chunk)
    const int nq = wid & 3;              // 0..3 n16 tile within CTA

    // whh slice (64 j rows x 1024 k) -> resident SMEM fp16, padded rows.
    for (int idx = tid; idx < NT * (RH / 2); idx += NTH) {
        int jl = idx >> 9;                  // /512
        int k2 = (idx & 511) * 2;
        float2 wv = *reinterpret_cast<const float2*>(
            &whh[(size_t)(jg0 + jl) * RH + k2]);
        __half2 p2;
        p2.x = __float2half(wv.x);
        p2.y = __float2half(wv.y);
        uint32_t off = (uint32_t)jl * W_PITCH + (uint32_t)k2 * 2u;
        *reinterpret_cast<__half2*>(smem + SW_OFF + off) = p2;
    }

    // ldmatrix addresses
    const uint32_t abuf = sb + SA_OFF + (uint32_t)half * A_BUF;
    const uint32_t a_off = (uint32_t)(lane & 15) * A_PITCH +
                           (uint32_t)(lane >> 4) * 16u;
    const uint32_t b_row = (uint32_t)((lane & 7) + ((lane & 16) ? 8 : 0));
    const uint32_t b_base = sw + ((uint32_t)nq * 16u + b_row) * W_PITCH +
                            (uint32_t)((lane >> 3) & 1) * 16u +
                            (uint32_t)half * (KH * 2);

    // Reduction / epilogue constants: thread owns batch row (tid>>3),
    // j columns (tid&7)*8 .. +7.
    const int erow = tid >> 3;
    const int e8 = tid & 7;
    const int ecol = e8 * 8;
    const int nq_r = e8 >> 1;            // scratch tile to read
    const int co = (e8 & 1) * 32;        // byte offset within tile row
    float wx[8], bs[8];
#pragma unroll
    for (int i = 0; i < 8; ++i) {
        wx[i] = whx[jg0 + ecol + i];
        bs[i] = bias_h[jg0 + ecol + i];
    }
    const int fr = lane >> 2;            // fragment row within m16 (and +8)
    const int fc8 = (lane & 3) * 8;      // fragment col byte offset (float2)

    char* const srp = smem + SR_OFF;
    char* const wrp = srp + (half * 4 + nq) * R_TILE;
    const int barid = 1 + half;
    unsigned int* const pollp = &g_cnt[m][half][0];
    unsigned int* const relp = &g_cnt[m][n >> 3][0];

    __syncthreads();

    for (int t = 0; t < RT; ++t) {
        // ---- warp-group phase: poll own half, stage own chunk, MMA ----
        const __half* h = &g_h[t & 1][(size_t)brow0 * RH + half * KH];

        if (lt == 0) {
            const unsigned int need = 8u * (unsigned int)t;
            while (ld_acq(pollp) < need) { }
        }
        bar_sync(barid);

        // Stage 32x512 fp16 chunk (128 threads of this warp-group).
#pragma unroll
        for (int i = 0; i < 16; ++i) {
            int sp = lt + i * 128;          // 16B segment id, 0..2047
            int row = sp >> 6;              // 64 segs per 1024B row
            int c16 = sp & 63;
            uint32_t doff = (uint32_t)row * A_PITCH + (uint32_t)c16 * 16u;
            const char* gs = (const char*)(h + (size_t)row * RH) + c16 * 16;
            cp16(abuf + doff, gs);
        }
        asm volatile("cp.async.commit_group;" ::: "memory");
        asm volatile("cp.async.wait_group 0;" ::: "memory");
        bar_sync(barid);

        float acc[16];
#pragma unroll
        for (int i = 0; i < 16; ++i) acc[i] = 0.f;

#pragma unroll 4
        for (int s = 0; s < 32; ++s) {
            uint32_t bf[4];
            ldsm4(b_base + (uint32_t)s * 32u, bf);
#pragma unroll
            for (int mt = 0; mt < 2; ++mt) {
                uint32_t af[4];
                ldsm4(abuf + a_off + (uint32_t)(mt * 16) * A_PITCH +
                      (uint32_t)s * 32u, af);
                mma_f16(acc + (mt * 2 + 0) * 4, af, bf[0], bf[1]);
                mma_f16(acc + (mt * 2 + 1) * 4, af, bf[2], bf[3]);
            }
        }

        // Write this warp's 32x16 partial tile to scratch.
#pragma unroll
        for (int mt = 0; mt < 2; ++mt) {
#pragma unroll
            for (int nt = 0; nt < 2; ++nt) {
                const float* d = acc + (mt * 2 + nt) * 4;
                int r = mt * 16 + fr;
                float2 v0; v0.x = d[0]; v0.y = d[1];
                float2 v1; v1.x = d[2]; v1.y = d[3];
                *reinterpret_cast<float2*>(wrp + r * R_PITCH + nt * 32 + fc8) = v0;
                *reinterpret_cast<float2*>(wrp + (r + 8) * R_PITCH + nt * 32 + fc8) = v1;
            }
        }
        __syncthreads();

        // ---- full-CTA phase: 2-way reduce, epilogue, store, release ----
        const char* r0 = srp + nq_r * R_TILE + erow * R_PITCH + co;
        float4 p00 = *reinterpret_cast<const float4*>(r0);
        float4 p01 = *reinterpret_cast<const float4*>(r0 + 16);
        const char* r1 = r0 + 4 * R_TILE;
        float4 p10 = *reinterpret_cast<const float4*>(r1);
        float4 p11 = *reinterpret_cast<const float4*>(r1 + 16);
        float sum[8];
        sum[0] = p00.x + p10.x; sum[1] = p00.y + p10.y;
        sum[2] = p00.z + p10.z; sum[3] = p00.w + p10.w;
        sum[4] = p01.x + p11.x; sum[5] = p01.y + p11.y;
        sum[6] = p01.z + p11.z; sum[7] = p01.w + p11.w;

        float xb = g_xT[t * RB + brow0 + erow];
        const int ob = (t + 1) & 1;
        uint32_t pk[4];
#pragma unroll
        for (int q = 0; q < 4; ++q) {
            float a = tanh_acc(sum[2 * q] + fmaf(xb, wx[2 * q], bs[2 * q]));
            float b = tanh_acc(sum[2 * q + 1] + fmaf(xb, wx[2 * q + 1], bs[2 * q + 1]));
            __half2 p2;
            p2.x = __float2half(a);
            p2.y = __float2half(b);
            pk[q] = *reinterpret_cast<uint32_t*>(&p2);
        }
        {
            size_t po = (size_t)(brow0 + erow) * RH + jg0 + ecol;
            uint4 u; u.x = pk[0]; u.y = pk[1]; u.z = pk[2]; u.w = pk[3];
            *reinterpret_cast<uint4*>(&g_h[ob][po]) = u;
        }

        __syncthreads();          // h stores + scratch reads complete
        if (tid == 0) red_rel_add1(relp);
    }
}

// p[b][c] = h_final[b] . wph[c] + bias_p[c]; final h is in buffer 0 (RT even).
__global__ void __launch_bounds__(RB, 1)
rnn_proj_kernel(const float* __restrict__ wph,
                const float* __restrict__ bias_p,
                float* __restrict__ out) {
    const int c = blockIdx.x;    // 0..9
    const int b = threadIdx.x;   // 0..255
    const __half* h = &g_h[0][(size_t)b * RH];
    const float* w = wph + (size_t)c * RH;
    float a0 = 0.0f, a1 = 0.0f;
#pragma unroll 4
    for (int k = 0; k < RH; k += 2) {
        __half2 h2 = *reinterpret_cast<const __half2*>(h + k);
        a0 = fmaf(__half2float(h2.x), w[k], a0);
        a1 = fmaf(__half2float(h2.y), w[k + 1], a1);
    }
    out[b * RC + c] = a0 + a1 + bias_p[c];
}

extern "C" void kernel_launch(void* const* d_in, const int* in_sizes, int n_in,
                              void* d_out, int out_size) {
    (void)in_sizes; (void)n_in; (void)out_size;
    const float* x      = (const float*)d_in[0];   // [B, T]
    const float* whx    = (const float*)d_in[1];   // [H, 1]
    const float* whh    = (const float*)d_in[2];   // [H, H]
    const float* bias_h = (const float*)d_in[3];   // [H]
    const float* wph    = (const float*)d_in[4];   // [C, H]
    const float* bias_p = (const float*)d_in[5];   // [C]
    float* out = (float*)d_out;                    // [B, C]

    cudaFuncSetAttribute(rnn_mma_kernel,
                         cudaFuncAttributeMaxDynamicSharedMemorySize, SMEM_BYTES);

    rnn_init_kernel<<<(RB * RH + NTH - 1) / NTH, NTH>>>(x);
    rnn_mma_kernel<<<NM * NN, NTH, SMEM_BYTES>>>(whx, whh, bias_h);
    rnn_proj_kernel<<<RC, RB>>>(wph, bias_p, out);
}